// round 2
// baseline (speedup 1.0000x reference)
#include <cuda_runtime.h>

#define HH 1024
#define WW 1024
#define NC 128
#define TS 32          // tile is 32x32 pixels
#define NTILES 32      // tiles per dimension
#define NITER 8

// Ping-pong accumulation buffers for iterations 0..6 (iter 7 accumulates
// straight into d_out). Zeroed by init_zero at the start of every launch.
__device__ float2 g_buf[NITER - 1][NC];

__global__ void init_zero_kernel(float2* __restrict__ out)
{
    int t = threadIdx.x;
    float2 z = make_float2(0.f, 0.f);
    for (int i = t; i < (NITER - 1) * NC; i += blockDim.x)
        ((float2*)g_buf)[i] = z;
    if (t < NC) out[t] = z;
}

__global__ __launch_bounds__(256)
void assign_kernel(const float* __restrict__ clusters_in,
                   const float* __restrict__ heat,
                   float2* __restrict__ d_out_f2,
                   int it)
{
    __shared__ float  s_warpmin[8];
    __shared__ int    s_cnt[4];
    __shared__ int    s_sidx[NC];
    __shared__ float2 s_scl[NC];
    __shared__ float2 s_acc[NC];

    const int tid = threadIdx.x;
    const int i0 = blockIdx.y * TS;
    const int j0 = blockIdx.x * TS;

    const float2* src = (it == 0) ? (const float2*)clusters_in
                                  : (const float2*)g_buf[it - 1];

    // ---- per-cluster distance from tile center (threads 0..127) ----
    float  cdist2 = 3.4e38f;
    float2 cl = make_float2(0.f, 0.f);
    if (tid < NC) {
        cl = src[tid];                       // (row, col)
        float cy = (float)i0 + 15.5f;
        float cx = (float)j0 + 15.5f;
        float dr = cy - cl.x;
        float dc = cx - cl.y;
        cdist2 = fmaf(dr, dr, dc * dc);
        s_acc[tid] = make_float2(0.f, 0.f);
    }

    // warp-level min reduction of center distances
    float m = cdist2;
    #pragma unroll
    for (int o = 16; o; o >>= 1)
        m = fminf(m, __shfl_xor_sync(0xffffffffu, m, o));
    if ((tid & 31) == 0)
        s_warpmin[tid >> 5] = m;
    __syncthreads();

    float mind2 = fminf(fminf(s_warpmin[0], s_warpmin[1]),
                        fminf(s_warpmin[2], s_warpmin[3]));

    // Survivor criterion: keep c iff dist(center,c) <= min_dist + 2r (+margin).
    // r = 15.5*sqrt(2) = 21.92; 2r = 43.84; margin absorbs fp rounding.
    float thr  = sqrtf(mind2) + 44.9f;
    float thr2 = thr * thr;

    bool pred = (tid < NC) && (cdist2 <= thr2);
    unsigned bal = __ballot_sync(0xffffffffu, pred);
    if ((tid & 31) == 0 && tid < NC)
        s_cnt[tid >> 5] = __popc(bal);
    __syncthreads();

    int c0 = s_cnt[0], c1 = s_cnt[1], c2 = s_cnt[2], c3 = s_cnt[3];
    int nsurv = c0 + c1 + c2 + c3;
    if (pred) {
        int w    = tid >> 5;
        int base = (w > 0 ? c0 : 0) + (w > 1 ? c1 : 0) + (w > 2 ? c2 : 0);
        int pos  = base + __popc(bal & ((1u << (tid & 31)) - 1u));
        s_sidx[pos] = tid;    // ascending cluster index -> tie-break preserved
        s_scl[pos]  = cl;
    }
    __syncthreads();

    // ---- pixel phase: each thread handles 4 consecutive columns of a row ----
    const int prow = tid >> 3;            // 0..31
    const int pcg  = (tid & 7) << 2;      // 0,4,...,28
    const float fi  = (float)(i0 + prow);
    const float fj0 = (float)(j0 + pcg);
    const float fj1 = fj0 + 1.0f;
    const float fj2 = fj0 + 2.0f;
    const float fj3 = fj0 + 3.0f;

    float b0 = 3.4e38f, b1 = 3.4e38f, b2 = 3.4e38f, b3 = 3.4e38f;
    int   s0 = 0, s1 = 0, s2 = 0, s3 = 0;

    for (int s = 0; s < nsurv; ++s) {
        float2 c = s_scl[s];
        float dr  = fi - c.x;
        float dr2 = dr * dr;

        float dc0 = fj0 - c.y;
        float d20 = fmaxf(fmaf(dc0, dc0, dr2), 1.0f);
        if (d20 < b0) { b0 = d20; s0 = s; }

        float dc1 = fj1 - c.y;
        float d21 = fmaxf(fmaf(dc1, dc1, dr2), 1.0f);
        if (d21 < b1) { b1 = d21; s1 = s; }

        float dc2 = fj2 - c.y;
        float d22 = fmaxf(fmaf(dc2, dc2, dr2), 1.0f);
        if (d22 < b2) { b2 = d22; s2 = s; }

        float dc3 = fj3 - c.y;
        float d23 = fmaxf(fmaf(dc3, dc3, dr2), 1.0f);
        if (d23 < b3) { b3 = d23; s3 = s; }
    }

    // ---- weights + shared-memory scatter-add ----
    const float4 h4 = *(const float4*)(heat + (i0 + prow) * WW + j0 + pcg);

    {
        int   ci = s_sidx[s0];
        float w  = h4.x / sqrtf(b0);
        atomicAdd(&s_acc[ci].x, fi  * w);
        atomicAdd(&s_acc[ci].y, fj0 * w);
    }
    {
        int   ci = s_sidx[s1];
        float w  = h4.y / sqrtf(b1);
        atomicAdd(&s_acc[ci].x, fi  * w);
        atomicAdd(&s_acc[ci].y, fj1 * w);
    }
    {
        int   ci = s_sidx[s2];
        float w  = h4.z / sqrtf(b2);
        atomicAdd(&s_acc[ci].x, fi  * w);
        atomicAdd(&s_acc[ci].y, fj2 * w);
    }
    {
        int   ci = s_sidx[s3];
        float w  = h4.w / sqrtf(b3);
        atomicAdd(&s_acc[ci].x, fi  * w);
        atomicAdd(&s_acc[ci].y, fj3 * w);
    }
    __syncthreads();

    // ---- flush nonzero cluster partials to the global accumulator ----
    if (tid < NC) {
        float2 v = s_acc[tid];
        float2* dst = (it == NITER - 1) ? d_out_f2 : g_buf[it];
        if (v.x != 0.f) atomicAdd(&dst[tid].x, v.x);
        if (v.y != 0.f) atomicAdd(&dst[tid].y, v.y);
    }
}

extern "C" void kernel_launch(void* const* d_in, const int* in_sizes, int n_in,
                              void* d_out, int out_size)
{
    // Identify inputs by size for robustness: clusters = 256 elems, heatmap = 1M.
    const float* clusters = (const float*)d_in[0];
    const float* heat     = (const float*)d_in[1];
    if (in_sizes[0] != NC * 2) {
        clusters = (const float*)d_in[1];
        heat     = (const float*)d_in[0];
    }
    float2* out = (float2*)d_out;

    init_zero_kernel<<<1, 256>>>(out);

    dim3 grid(NTILES, NTILES);
    for (int it = 0; it < NITER; ++it)
        assign_kernel<<<grid, 256>>>(clusters, heat, out, it);
}

// round 3
// speedup vs baseline: 4.9699x; 4.9699x over previous
#include <cuda_runtime.h>

#define HH 1024
#define WW 1024
#define NC 128
#define TS 32          // tile is 32x32 pixels
#define NTILES 32      // tiles per dimension
#define NITER 8

// Ping-pong accumulation buffers for iterations 0..6 (iter 7 accumulates
// straight into d_out). Zeroed by init_zero at the start of every launch.
__device__ float2 g_buf[NITER - 1][NC];

__global__ void init_zero_kernel(float2* __restrict__ out)
{
    int t = threadIdx.x;
    float2 z = make_float2(0.f, 0.f);
    for (int i = t; i < (NITER - 1) * NC; i += blockDim.x)
        ((float2*)g_buf)[i] = z;
    if (t < NC) out[t] = z;
}

__global__ __launch_bounds__(256)
void assign_kernel(const float* __restrict__ clusters_in,
                   const float* __restrict__ heat,
                   float2* __restrict__ d_out_f2,
                   int it)
{
    __shared__ float  s_warpmin[8];
    __shared__ int    s_cnt[4];
    __shared__ int    s_sidx[NC];
    __shared__ float2 s_all[NC];
    __shared__ float2 s_scl[NC];
    __shared__ float2 s_acc[NC];

    const int tid = threadIdx.x;
    const int i0 = blockIdx.y * TS;
    const int j0 = blockIdx.x * TS;

    const float2* src = (it == 0) ? (const float2*)clusters_in
                                  : (const float2*)g_buf[it - 1];

    // ---- per-cluster distance from tile center (threads 0..127) ----
    float  cdist2 = 3.4e38f;
    float2 cl = make_float2(0.f, 0.f);
    if (tid < NC) {
        cl = src[tid];                       // (row, col)
        s_all[tid] = cl;
        float cy = (float)i0 + 15.5f;
        float cx = (float)j0 + 15.5f;
        float dr = cy - cl.x;
        float dc = cx - cl.y;
        cdist2 = __fadd_rn(__fmul_rn(dr, dr), __fmul_rn(dc, dc));
        s_acc[tid] = make_float2(0.f, 0.f);
    }

    // warp-level min reduction of center distances
    float m = cdist2;
    #pragma unroll
    for (int o = 16; o; o >>= 1)
        m = fminf(m, __shfl_xor_sync(0xffffffffu, m, o));
    if ((tid & 31) == 0)
        s_warpmin[tid >> 5] = m;
    __syncthreads();

    float mind2 = fminf(fminf(s_warpmin[0], s_warpmin[1]),
                        fminf(s_warpmin[2], s_warpmin[3]));

    // Survivor criterion: keep c iff dist(center,c) <= min_dist + 2r (+margin).
    // r = 15.5*sqrt(2) = 21.92; 2r = 43.84; margin absorbs fp rounding.
    float thr  = sqrtf(mind2) + 44.9f;
    float thr2 = thr * thr;

    // Dedupe: a cluster with coordinates identical to a LOWER-index cluster
    // can never win the strict-< argmin for any pixel -> drop it. This is
    // exact w.r.t. the reference tie-break and collapses the degenerate
    // "127 clusters at (0,0)" iterations back to 1 survivor.
    bool uniq = true;
    if (tid < NC) {
        for (int k = 0; k < tid; ++k) {
            float2 o = s_all[k];
            if (o.x == cl.x && o.y == cl.y) { uniq = false; break; }
        }
    }

    bool pred = (tid < NC) && uniq && (cdist2 <= thr2);
    unsigned bal = __ballot_sync(0xffffffffu, pred);
    if ((tid & 31) == 0 && tid < NC)
        s_cnt[tid >> 5] = __popc(bal);
    __syncthreads();

    int c0 = s_cnt[0], c1 = s_cnt[1], c2 = s_cnt[2], c3 = s_cnt[3];
    int nsurv = c0 + c1 + c2 + c3;
    if (pred) {
        int w    = tid >> 5;
        int base = (w > 0 ? c0 : 0) + (w > 1 ? c1 : 0) + (w > 2 ? c2 : 0);
        int pos  = base + __popc(bal & ((1u << (tid & 31)) - 1u));
        s_sidx[pos] = tid;    // ascending cluster index -> tie-break preserved
        s_scl[pos]  = cl;
    }
    __syncthreads();

    // ---- pixel phase: each thread handles 4 consecutive columns of a row ----
    const int prow = tid >> 3;            // 0..31
    const int pcg  = (tid & 7) << 2;      // 0,4,...,28
    const float fi  = (float)(i0 + prow);
    const float fj0 = (float)(j0 + pcg);
    const float fj1 = fj0 + 1.0f;
    const float fj2 = fj0 + 2.0f;
    const float fj3 = fj0 + 3.0f;

    float b0 = 3.4e38f, b1 = 3.4e38f, b2 = 3.4e38f, b3 = 3.4e38f;
    int   s0 = 0, s1 = 0, s2 = 0, s3 = 0;

    for (int s = 0; s < nsurv; ++s) {
        float2 c = s_scl[s];
        float dr  = fi - c.x;
        float dr2 = __fmul_rn(dr, dr);

        // Match reference arithmetic exactly: dr*dr + dc*dc (no fma contraction)
        float dc0 = fj0 - c.y;
        float d20 = fmaxf(__fadd_rn(dr2, __fmul_rn(dc0, dc0)), 1.0f);
        if (d20 < b0) { b0 = d20; s0 = s; }

        float dc1 = fj1 - c.y;
        float d21 = fmaxf(__fadd_rn(dr2, __fmul_rn(dc1, dc1)), 1.0f);
        if (d21 < b1) { b1 = d21; s1 = s; }

        float dc2 = fj2 - c.y;
        float d22 = fmaxf(__fadd_rn(dr2, __fmul_rn(dc2, dc2)), 1.0f);
        if (d22 < b2) { b2 = d22; s2 = s; }

        float dc3 = fj3 - c.y;
        float d23 = fmaxf(__fadd_rn(dr2, __fmul_rn(dc3, dc3)), 1.0f);
        if (d23 < b3) { b3 = d23; s3 = s; }
    }

    // ---- weights ----
    const float4 h4 = *(const float4*)(heat + (i0 + prow) * WW + j0 + pcg);
    float w0 = h4.x / sqrtf(b0);
    float w1 = h4.y / sqrtf(b1);
    float w2 = h4.z / sqrtf(b2);
    float w3 = h4.w / sqrtf(b3);

    // ---- scatter-add with warp-uniform fast path ----
    const unsigned full = 0xffffffffu;
    bool same4 = (s0 == s1) & (s0 == s2) & (s0 == s3);
    int  sref  = __shfl_sync(full, s0, 0);
    bool uni   = __all_sync(full, same4 && (s0 == sref));

    if (uni) {
        // all 128 pixels of this warp share one winner: reduce then 2 atomics
        float lx = fi * ((w0 + w1) + (w2 + w3));
        float ly = (fj0 * w0 + fj1 * w1) + (fj2 * w2 + fj3 * w3);
        #pragma unroll
        for (int o = 16; o; o >>= 1) {
            lx += __shfl_xor_sync(full, lx, o);
            ly += __shfl_xor_sync(full, ly, o);
        }
        if ((tid & 31) == 0) {
            int ci = s_sidx[sref];
            atomicAdd(&s_acc[ci].x, lx);
            atomicAdd(&s_acc[ci].y, ly);
        }
    } else {
        {
            int ci = s_sidx[s0];
            atomicAdd(&s_acc[ci].x, fi  * w0);
            atomicAdd(&s_acc[ci].y, fj0 * w0);
        }
        {
            int ci = s_sidx[s1];
            atomicAdd(&s_acc[ci].x, fi  * w1);
            atomicAdd(&s_acc[ci].y, fj1 * w1);
        }
        {
            int ci = s_sidx[s2];
            atomicAdd(&s_acc[ci].x, fi  * w2);
            atomicAdd(&s_acc[ci].y, fj2 * w2);
        }
        {
            int ci = s_sidx[s3];
            atomicAdd(&s_acc[ci].x, fi  * w3);
            atomicAdd(&s_acc[ci].y, fj3 * w3);
        }
    }
    __syncthreads();

    // ---- flush nonzero cluster partials to the global accumulator ----
    if (tid < NC) {
        float2 v = s_acc[tid];
        float2* dst = (it == NITER - 1) ? d_out_f2 : g_buf[it];
        if (v.x != 0.f) atomicAdd(&dst[tid].x, v.x);
        if (v.y != 0.f) atomicAdd(&dst[tid].y, v.y);
    }
}

extern "C" void kernel_launch(void* const* d_in, const int* in_sizes, int n_in,
                              void* d_out, int out_size)
{
    // Identify inputs by size for robustness: clusters = 256 elems, heatmap = 1M.
    const float* clusters = (const float*)d_in[0];
    const float* heat     = (const float*)d_in[1];
    if (in_sizes[0] != NC * 2) {
        clusters = (const float*)d_in[1];
        heat     = (const float*)d_in[0];
    }
    float2* out = (float2*)d_out;

    init_zero_kernel<<<1, 256>>>(out);

    dim3 grid(NTILES, NTILES);
    for (int it = 0; it < NITER; ++it)
        assign_kernel<<<grid, 256>>>(clusters, heat, out, it);
}

// round 4
// speedup vs baseline: 6.9478x; 1.3980x over previous
#include <cuda_runtime.h>

#define HH 1024
#define WW 1024
#define NC 128
#define TS 32          // tile is 32x32 pixels
#define NTILES 32      // tiles per dimension
#define NITER 8
#define NREP 32        // accumulator replicas (contention spreading)

// Per-iteration replicated accumulators. g_part[it][r][c], zeroed each launch.
// Iteration it scatters into replica (blockIdx.x & 31); iteration it+1 reads
// the sum over replicas. Final iteration's replicas are folded into d_out by
// final_reduce_kernel.
__device__ float2 g_part[NITER][NREP][NC];

__global__ void init_zero_kernel()
{
    float4 z4 = make_float4(0.f, 0.f, 0.f, 0.f);
    float4* p = (float4*)g_part;
    int n = (int)(sizeof(g_part) / sizeof(float4));
    for (int i = blockIdx.x * blockDim.x + threadIdx.x; i < n;
         i += gridDim.x * blockDim.x)
        p[i] = z4;
}

__global__ void final_reduce_kernel(float2* __restrict__ out)
{
    int c = threadIdx.x;            // 128 threads
    float x = 0.f, y = 0.f;
    #pragma unroll
    for (int r = 0; r < NREP; ++r) {
        float2 v = g_part[NITER - 1][r][c];
        x += v.x; y += v.y;
    }
    out[c] = make_float2(x, y);
}

__global__ __launch_bounds__(256)
void assign_kernel(const float* __restrict__ clusters_in,
                   const float* __restrict__ heat,
                   int it)
{
    __shared__ float  s_warpmin[8];
    __shared__ int    s_cnt[4];
    __shared__ int    s_sidx[NC];
    __shared__ float2 s_all[NC];
    __shared__ float2 s_scl[NC];
    __shared__ float2 s_acc[NC];

    const int tid = threadIdx.x;
    const int i0 = blockIdx.y * TS;
    const int j0 = blockIdx.x * TS;

    // ---- per-cluster distance from tile center (threads 0..127) ----
    float  cdist2 = 3.4e38f;
    float2 cl = make_float2(0.f, 0.f);
    if (tid < NC) {
        if (it == 0) {
            cl = ((const float2*)clusters_in)[tid];   // (row, col)
        } else {
            float x = 0.f, y = 0.f;
            #pragma unroll
            for (int r = 0; r < NREP; ++r) {
                float2 v = g_part[it - 1][r][tid];
                x += v.x; y += v.y;
            }
            cl = make_float2(x, y);
        }
        s_all[tid] = cl;
        float cy = (float)i0 + 15.5f;
        float cx = (float)j0 + 15.5f;
        float dr = cy - cl.x;
        float dc = cx - cl.y;
        cdist2 = __fadd_rn(__fmul_rn(dr, dr), __fmul_rn(dc, dc));
        s_acc[tid] = make_float2(0.f, 0.f);
    }

    // warp-level min reduction of center distances
    float m = cdist2;
    #pragma unroll
    for (int o = 16; o; o >>= 1)
        m = fminf(m, __shfl_xor_sync(0xffffffffu, m, o));
    if ((tid & 31) == 0)
        s_warpmin[tid >> 5] = m;
    __syncthreads();

    float mind2 = fminf(fminf(s_warpmin[0], s_warpmin[1]),
                        fminf(s_warpmin[2], s_warpmin[3]));

    // Survivor criterion: keep c iff dist(center,c) <= min_dist + 2r (+margin).
    // r = 15.5*sqrt(2) = 21.92; 2r = 43.84; margin absorbs fp rounding.
    float thr  = sqrtf(mind2) + 44.9f;
    float thr2 = thr * thr;

    // Dedupe: a cluster with coordinates identical to a LOWER-index cluster
    // can never win the strict-< argmin for any pixel -> drop it (exact
    // w.r.t. the reference tie-break). Branch-free scan: independent loads,
    // fully pipelined (no load->branch dependency chain).
    bool uniq = true;
    if (tid < NC) {
        #pragma unroll 4
        for (int k = 0; k < tid; ++k) {
            float2 o = s_all[k];
            uniq &= !((o.x == cl.x) & (o.y == cl.y));
        }
    }

    bool pred = (tid < NC) && uniq && (cdist2 <= thr2);
    unsigned bal = __ballot_sync(0xffffffffu, pred);
    if ((tid & 31) == 0 && tid < NC)
        s_cnt[tid >> 5] = __popc(bal);
    __syncthreads();

    int c0 = s_cnt[0], c1 = s_cnt[1], c2 = s_cnt[2], c3 = s_cnt[3];
    int nsurv = c0 + c1 + c2 + c3;
    if (pred) {
        int w    = tid >> 5;
        int base = (w > 0 ? c0 : 0) + (w > 1 ? c1 : 0) + (w > 2 ? c2 : 0);
        int pos  = base + __popc(bal & ((1u << (tid & 31)) - 1u));
        s_sidx[pos] = tid;    // ascending cluster index -> tie-break preserved
        s_scl[pos]  = cl;
    }
    __syncthreads();

    // ---- pixel phase: each thread handles 4 consecutive columns of a row ----
    const int prow = tid >> 3;            // 0..31
    const int pcg  = (tid & 7) << 2;      // 0,4,...,28
    const float fi  = (float)(i0 + prow);
    const float fj0 = (float)(j0 + pcg);
    const float fj1 = fj0 + 1.0f;
    const float fj2 = fj0 + 2.0f;
    const float fj3 = fj0 + 3.0f;

    float b0 = 3.4e38f, b1 = 3.4e38f, b2 = 3.4e38f, b3 = 3.4e38f;
    int   s0 = 0, s1 = 0, s2 = 0, s3 = 0;

    for (int s = 0; s < nsurv; ++s) {
        float2 c = s_scl[s];
        float dr  = fi - c.x;
        float dr2 = __fmul_rn(dr, dr);

        // Match reference arithmetic exactly: dr*dr + dc*dc (no fma contraction)
        float dc0 = fj0 - c.y;
        float d20 = fmaxf(__fadd_rn(dr2, __fmul_rn(dc0, dc0)), 1.0f);
        if (d20 < b0) { b0 = d20; s0 = s; }

        float dc1 = fj1 - c.y;
        float d21 = fmaxf(__fadd_rn(dr2, __fmul_rn(dc1, dc1)), 1.0f);
        if (d21 < b1) { b1 = d21; s1 = s; }

        float dc2 = fj2 - c.y;
        float d22 = fmaxf(__fadd_rn(dr2, __fmul_rn(dc2, dc2)), 1.0f);
        if (d22 < b2) { b2 = d22; s2 = s; }

        float dc3 = fj3 - c.y;
        float d23 = fmaxf(__fadd_rn(dr2, __fmul_rn(dc3, dc3)), 1.0f);
        if (d23 < b3) { b3 = d23; s3 = s; }
    }

    // ---- weights (h * rsqrt(d2); ~1e-7 rel vs exact div/sqrt) ----
    const float4 h4 = *(const float4*)(heat + (i0 + prow) * WW + j0 + pcg);
    float w0 = h4.x * __frsqrt_rn(b0);
    float w1 = h4.y * __frsqrt_rn(b1);
    float w2 = h4.z * __frsqrt_rn(b2);
    float w3 = h4.w * __frsqrt_rn(b3);

    // ---- scatter-add with warp-uniform fast path ----
    const unsigned full = 0xffffffffu;
    bool same4 = (s0 == s1) & (s0 == s2) & (s0 == s3);
    int  sref  = __shfl_sync(full, s0, 0);
    bool uni   = __all_sync(full, same4 && (s0 == sref));

    if (uni) {
        // all 128 pixels of this warp share one winner: reduce then 2 atomics
        float lx = fi * ((w0 + w1) + (w2 + w3));
        float ly = (fj0 * w0 + fj1 * w1) + (fj2 * w2 + fj3 * w3);
        #pragma unroll
        for (int o = 16; o; o >>= 1) {
            lx += __shfl_xor_sync(full, lx, o);
            ly += __shfl_xor_sync(full, ly, o);
        }
        if ((tid & 31) == 0) {
            int ci = s_sidx[sref];
            atomicAdd(&s_acc[ci].x, lx);
            atomicAdd(&s_acc[ci].y, ly);
        }
    } else {
        {
            int ci = s_sidx[s0];
            atomicAdd(&s_acc[ci].x, fi  * w0);
            atomicAdd(&s_acc[ci].y, fj0 * w0);
        }
        {
            int ci = s_sidx[s1];
            atomicAdd(&s_acc[ci].x, fi  * w1);
            atomicAdd(&s_acc[ci].y, fj1 * w1);
        }
        {
            int ci = s_sidx[s2];
            atomicAdd(&s_acc[ci].x, fi  * w2);
            atomicAdd(&s_acc[ci].y, fj2 * w2);
        }
        {
            int ci = s_sidx[s3];
            atomicAdd(&s_acc[ci].x, fi  * w3);
            atomicAdd(&s_acc[ci].y, fj3 * w3);
        }
    }
    __syncthreads();

    // ---- flush nonzero cluster partials to this block's replica ----
    if (tid < NC) {
        float2 v = s_acc[tid];
        float2* dst = g_part[it][blockIdx.x & (NREP - 1)];
        if (v.x != 0.f) atomicAdd(&dst[tid].x, v.x);
        if (v.y != 0.f) atomicAdd(&dst[tid].y, v.y);
    }
}

extern "C" void kernel_launch(void* const* d_in, const int* in_sizes, int n_in,
                              void* d_out, int out_size)
{
    // Identify inputs by size for robustness: clusters = 256 elems, heatmap = 1M.
    const float* clusters = (const float*)d_in[0];
    const float* heat     = (const float*)d_in[1];
    if (in_sizes[0] != NC * 2) {
        clusters = (const float*)d_in[1];
        heat     = (const float*)d_in[0];
    }
    float2* out = (float2*)d_out;

    init_zero_kernel<<<64, 256>>>();

    dim3 grid(NTILES, NTILES);
    for (int it = 0; it < NITER; ++it)
        assign_kernel<<<grid, 256>>>(clusters, heat, it);

    final_reduce_kernel<<<1, NC>>>(out);
}